// round 3
// baseline (speedup 1.0000x reference)
#include <cuda_runtime.h>
#include <cstdint>

// ModelVoxel: out[p] = f[i,j,k] with i,j,k = (int)clip((x[p]+1)/h, 0, 255),
// h = 2/255, f is 256^3 fp32 (64 MB, fits in GB300's ~126 MB L2).
//
// Layout trick: x is (N,3) fp32 AoS. 4 consecutive points = 12 floats =
// exactly 3 float4s, so each thread handles 4 points with three coalesced
// LDG.128, four random gathers, and one STG.128.

static __device__ __forceinline__ int vox1(float v) {
    const float h = 2.0f / 255.0f;           // replicate reference's fp32 h
    float p = (v + 1.0f) / h;                // same op order as reference
    p = fminf(fmaxf(p, 0.0f), 255.0f);       // clip
    return (int)p;                           // truncation == astype(int32) (p >= 0)
}

__global__ void __launch_bounds__(256) voxel_gather_kernel(
    const float4* __restrict__ x4,   // 3 float4s per 4 points
    const float*  __restrict__ f,    // 256^3 grid
    float4*       __restrict__ out4, // 1 float4 per 4 points
    int n4)                          // number of 4-point groups
{
    int t = blockIdx.x * blockDim.x + threadIdx.x;
    if (t >= n4) return;

    const float4* p = x4 + 3 * (size_t)t;
    float4 a = __ldg(p + 0);
    float4 b = __ldg(p + 1);
    float4 c = __ldg(p + 2);

    // point 0: (a.x, a.y, a.z)  point 1: (a.w, b.x, b.y)
    // point 2: (b.z, b.w, c.x)  point 3: (c.y, c.z, c.w)
    int i0 = (vox1(a.x) << 16) | (vox1(a.y) << 8) | vox1(a.z);
    int i1 = (vox1(a.w) << 16) | (vox1(b.x) << 8) | vox1(b.y);
    int i2 = (vox1(b.z) << 16) | (vox1(b.w) << 8) | vox1(c.x);
    int i3 = (vox1(c.y) << 16) | (vox1(c.z) << 8) | vox1(c.w);

    float4 o;
    o.x = __ldg(f + i0);
    o.y = __ldg(f + i1);
    o.z = __ldg(f + i2);
    o.w = __ldg(f + i3);
    out4[t] = o;
}

// Tail handler for n not divisible by 4 (not needed for 16777216, but cheap).
__global__ void voxel_gather_tail_kernel(
    const float* __restrict__ x,
    const float* __restrict__ f,
    float*       __restrict__ out,
    int start, int n)
{
    int i = start + blockIdx.x * blockDim.x + threadIdx.x;
    if (i >= n) return;
    int ix = vox1(x[3 * (size_t)i + 0]);
    int iy = vox1(x[3 * (size_t)i + 1]);
    int iz = vox1(x[3 * (size_t)i + 2]);
    out[i] = __ldg(f + ((ix << 16) | (iy << 8) | iz));
}

extern "C" void kernel_launch(void* const* d_in, const int* in_sizes, int n_in,
                              void* d_out, int out_size) {
    const float* x = (const float*)d_in[0];   // (N, 3) fp32
    const float* f = (const float*)d_in[1];   // (256,256,256) fp32
    float* out = (float*)d_out;               // (N,) fp32

    int n  = in_sizes[0] / 3;                 // number of points
    int n4 = n / 4;

    if (n4 > 0) {
        int threads = 256;
        int blocks = (n4 + threads - 1) / threads;
        voxel_gather_kernel<<<blocks, threads>>>(
            (const float4*)x, f, (float4*)out, n4);
    }
    int rem_start = n4 * 4;
    if (rem_start < n) {
        int rem = n - rem_start;
        voxel_gather_tail_kernel<<<(rem + 255) / 256, 256>>>(
            x, f, out, rem_start, n);
    }
}

// round 4
// speedup vs baseline: 1.0003x; 1.0003x over previous
#include <cuda_runtime.h>
#include <cstdint>

// ModelVoxel: out[p] = f[i,j,k] with i,j,k = (int)clip((x[p]+1)/h, 0, 255),
// h = 2/255, f is 256^3 fp32 (64 MB, fits in GB300's ~126 MB L2).
//
// Layout trick: x is (N,3) fp32 AoS. 4 consecutive points = 12 floats =
// exactly 3 float4s, so each thread handles 4 points with three coalesced
// LDG.128, four random gathers, and one STG.128.

static __device__ __forceinline__ int vox1(float v) {
    const float h = 2.0f / 255.0f;           // replicate reference's fp32 h
    float p = (v + 1.0f) / h;                // same op order as reference
    p = fminf(fmaxf(p, 0.0f), 255.0f);       // clip
    return (int)p;                           // truncation == astype(int32) (p >= 0)
}

__global__ void __launch_bounds__(256) voxel_gather_kernel(
    const float4* __restrict__ x4,   // 3 float4s per 4 points
    const float*  __restrict__ f,    // 256^3 grid
    float4*       __restrict__ out4, // 1 float4 per 4 points
    int n4)                          // number of 4-point groups
{
    int t = blockIdx.x * blockDim.x + threadIdx.x;
    if (t >= n4) return;

    const float4* p = x4 + 3 * (size_t)t;
    float4 a = __ldg(p + 0);
    float4 b = __ldg(p + 1);
    float4 c = __ldg(p + 2);

    // point 0: (a.x, a.y, a.z)  point 1: (a.w, b.x, b.y)
    // point 2: (b.z, b.w, c.x)  point 3: (c.y, c.z, c.w)
    int i0 = (vox1(a.x) << 16) | (vox1(a.y) << 8) | vox1(a.z);
    int i1 = (vox1(a.w) << 16) | (vox1(b.x) << 8) | vox1(b.y);
    int i2 = (vox1(b.z) << 16) | (vox1(b.w) << 8) | vox1(c.x);
    int i3 = (vox1(c.y) << 16) | (vox1(c.z) << 8) | vox1(c.w);

    float4 o;
    o.x = __ldg(f + i0);
    o.y = __ldg(f + i1);
    o.z = __ldg(f + i2);
    o.w = __ldg(f + i3);
    out4[t] = o;
}

// Tail handler for n not divisible by 4 (not needed for 16777216, but cheap).
__global__ void voxel_gather_tail_kernel(
    const float* __restrict__ x,
    const float* __restrict__ f,
    float*       __restrict__ out,
    int start, int n)
{
    int i = start + blockIdx.x * blockDim.x + threadIdx.x;
    if (i >= n) return;
    int ix = vox1(x[3 * (size_t)i + 0]);
    int iy = vox1(x[3 * (size_t)i + 1]);
    int iz = vox1(x[3 * (size_t)i + 2]);
    out[i] = __ldg(f + ((ix << 16) | (iy << 8) | iz));
}

extern "C" void kernel_launch(void* const* d_in, const int* in_sizes, int n_in,
                              void* d_out, int out_size) {
    const float* x = (const float*)d_in[0];   // (N, 3) fp32
    const float* f = (const float*)d_in[1];   // (256,256,256) fp32
    float* out = (float*)d_out;               // (N,) fp32

    int n  = in_sizes[0] / 3;                 // number of points
    int n4 = n / 4;

    if (n4 > 0) {
        int threads = 256;
        int blocks = (n4 + threads - 1) / threads;
        voxel_gather_kernel<<<blocks, threads>>>(
            (const float4*)x, f, (float4*)out, n4);
    }
    int rem_start = n4 * 4;
    if (rem_start < n) {
        int rem = n - rem_start;
        voxel_gather_tail_kernel<<<(rem + 255) / 256, 256>>>(
            x, f, out, rem_start, n);
    }
}

// round 5
// speedup vs baseline: 1.0010x; 1.0007x over previous
#include <cuda_runtime.h>
#include <cstdint>

// ModelVoxel: out[p] = f[i,j,k] with i,j,k = (int)clip((x[p]+1)/h, 0, 255),
// h = 2/255, f is 256^3 fp32 (64 MB, fits in GB300's ~126 MB L2).
//
// Layout trick: x is (N,3) fp32 AoS. 4 consecutive points = 12 floats =
// exactly 3 float4s, so each thread handles 4 points with three coalesced
// LDG.128, four random gathers, and one STG.128.

static __device__ __forceinline__ int vox1(float v) {
    const float h = 2.0f / 255.0f;           // replicate reference's fp32 h
    float p = (v + 1.0f) / h;                // same op order as reference
    p = fminf(fmaxf(p, 0.0f), 255.0f);       // clip
    return (int)p;                           // truncation == astype(int32) (p >= 0)
}

__global__ void __launch_bounds__(256) voxel_gather_kernel(
    const float4* __restrict__ x4,   // 3 float4s per 4 points
    const float*  __restrict__ f,    // 256^3 grid
    float4*       __restrict__ out4, // 1 float4 per 4 points
    int n4)                          // number of 4-point groups
{
    int t = blockIdx.x * blockDim.x + threadIdx.x;
    if (t >= n4) return;

    const float4* p = x4 + 3 * (size_t)t;
    float4 a = __ldg(p + 0);
    float4 b = __ldg(p + 1);
    float4 c = __ldg(p + 2);

    // point 0: (a.x, a.y, a.z)  point 1: (a.w, b.x, b.y)
    // point 2: (b.z, b.w, c.x)  point 3: (c.y, c.z, c.w)
    int i0 = (vox1(a.x) << 16) | (vox1(a.y) << 8) | vox1(a.z);
    int i1 = (vox1(a.w) << 16) | (vox1(b.x) << 8) | vox1(b.y);
    int i2 = (vox1(b.z) << 16) | (vox1(b.w) << 8) | vox1(c.x);
    int i3 = (vox1(c.y) << 16) | (vox1(c.z) << 8) | vox1(c.w);

    float4 o;
    o.x = __ldg(f + i0);
    o.y = __ldg(f + i1);
    o.z = __ldg(f + i2);
    o.w = __ldg(f + i3);
    out4[t] = o;
}

// Tail handler for n not divisible by 4 (not needed for 16777216, but cheap).
__global__ void voxel_gather_tail_kernel(
    const float* __restrict__ x,
    const float* __restrict__ f,
    float*       __restrict__ out,
    int start, int n)
{
    int i = start + blockIdx.x * blockDim.x + threadIdx.x;
    if (i >= n) return;
    int ix = vox1(x[3 * (size_t)i + 0]);
    int iy = vox1(x[3 * (size_t)i + 1]);
    int iz = vox1(x[3 * (size_t)i + 2]);
    out[i] = __ldg(f + ((ix << 16) | (iy << 8) | iz));
}

extern "C" void kernel_launch(void* const* d_in, const int* in_sizes, int n_in,
                              void* d_out, int out_size) {
    const float* x = (const float*)d_in[0];   // (N, 3) fp32
    const float* f = (const float*)d_in[1];   // (256,256,256) fp32
    float* out = (float*)d_out;               // (N,) fp32

    int n  = in_sizes[0] / 3;                 // number of points
    int n4 = n / 4;

    if (n4 > 0) {
        int threads = 256;
        int blocks = (n4 + threads - 1) / threads;
        voxel_gather_kernel<<<blocks, threads>>>(
            (const float4*)x, f, (float4*)out, n4);
    }
    int rem_start = n4 * 4;
    if (rem_start < n) {
        int rem = n - rem_start;
        voxel_gather_tail_kernel<<<(rem + 255) / 256, 256>>>(
            x, f, out, rem_start, n);
    }
}

// round 6
// speedup vs baseline: 1.0052x; 1.0042x over previous
#include <cuda_runtime.h>
#include <cstdint>

// ModelVoxel: out[p] = f[i,j,k] with i,j,k = (int)clip((x[p]+1)/h, 0, 255),
// h = 2/255, f is 256^3 fp32 (64 MB, fits in GB300's ~126 MB L2).
//
// Layout trick: x is (N,3) fp32 AoS. 4 consecutive points = 12 floats =
// exactly 3 float4s, so each thread handles 4 points with three coalesced
// LDG.128, four random gathers, and one STG.128.

static __device__ __forceinline__ int vox1(float v) {
    const float h = 2.0f / 255.0f;           // replicate reference's fp32 h
    float p = (v + 1.0f) / h;                // same op order as reference
    p = fminf(fmaxf(p, 0.0f), 255.0f);       // clip
    return (int)p;                           // truncation == astype(int32) (p >= 0)
}

__global__ void __launch_bounds__(256) voxel_gather_kernel(
    const float4* __restrict__ x4,   // 3 float4s per 4 points
    const float*  __restrict__ f,    // 256^3 grid
    float4*       __restrict__ out4, // 1 float4 per 4 points
    int n4)                          // number of 4-point groups
{
    int t = blockIdx.x * blockDim.x + threadIdx.x;
    if (t >= n4) return;

    const float4* p = x4 + 3 * (size_t)t;
    float4 a = __ldg(p + 0);
    float4 b = __ldg(p + 1);
    float4 c = __ldg(p + 2);

    // point 0: (a.x, a.y, a.z)  point 1: (a.w, b.x, b.y)
    // point 2: (b.z, b.w, c.x)  point 3: (c.y, c.z, c.w)
    int i0 = (vox1(a.x) << 16) | (vox1(a.y) << 8) | vox1(a.z);
    int i1 = (vox1(a.w) << 16) | (vox1(b.x) << 8) | vox1(b.y);
    int i2 = (vox1(b.z) << 16) | (vox1(b.w) << 8) | vox1(c.x);
    int i3 = (vox1(c.y) << 16) | (vox1(c.z) << 8) | vox1(c.w);

    float4 o;
    o.x = __ldg(f + i0);
    o.y = __ldg(f + i1);
    o.z = __ldg(f + i2);
    o.w = __ldg(f + i3);
    out4[t] = o;
}

// Tail handler for n not divisible by 4 (not needed for 16777216, but cheap).
__global__ void voxel_gather_tail_kernel(
    const float* __restrict__ x,
    const float* __restrict__ f,
    float*       __restrict__ out,
    int start, int n)
{
    int i = start + blockIdx.x * blockDim.x + threadIdx.x;
    if (i >= n) return;
    int ix = vox1(x[3 * (size_t)i + 0]);
    int iy = vox1(x[3 * (size_t)i + 1]);
    int iz = vox1(x[3 * (size_t)i + 2]);
    out[i] = __ldg(f + ((ix << 16) | (iy << 8) | iz));
}

extern "C" void kernel_launch(void* const* d_in, const int* in_sizes, int n_in,
                              void* d_out, int out_size) {
    const float* x = (const float*)d_in[0];   // (N, 3) fp32
    const float* f = (const float*)d_in[1];   // (256,256,256) fp32
    float* out = (float*)d_out;               // (N,) fp32

    int n  = in_sizes[0] / 3;                 // number of points
    int n4 = n / 4;

    if (n4 > 0) {
        int threads = 256;
        int blocks = (n4 + threads - 1) / threads;
        voxel_gather_kernel<<<blocks, threads>>>(
            (const float4*)x, f, (float4*)out, n4);
    }
    int rem_start = n4 * 4;
    if (rem_start < n) {
        int rem = n - rem_start;
        voxel_gather_tail_kernel<<<(rem + 255) / 256, 256>>>(
            x, f, out, rem_start, n);
    }
}

// round 8
// speedup vs baseline: 1.0495x; 1.0441x over previous
#include <cuda_runtime.h>
#include <cstdint>

// ModelVoxel: out[p] = f[i,j,k] with i,j,k = (int)clip((x[p]+1)/h, 0, 255),
// h = 2/255, f is 256^3 fp32 (64 MB, fits in GB300's ~126 MB L2).
//
// R7: cache-priority separation, fixed encoding.
//  - x (192 MB, read-once)  -> __ldcs (L2 evict-first, don't pollute)
//  - out (64 MB, write-once)-> __stcs (streaming store)
//  - f  (64 MB gather table)-> ld.global.nc.L2::cache_hint with a
//    createpolicy.fractional.L2::evict_last policy register (ptxas rejects
//    the immediate .L2::evict_last form on scalar loads on sm_103).
// Goal: keep f fully L2-resident so the 16.7M random gathers never hit DRAM.

static __device__ __forceinline__ int vox1(float v) {
    const float h = 2.0f / 255.0f;           // replicate reference's fp32 h
    float p = (v + 1.0f) / h;                // same op order as reference
    p = fminf(fmaxf(p, 0.0f), 255.0f);       // clip
    return (int)p;                           // truncation == astype(int32) (p >= 0)
}

static __device__ __forceinline__ uint64_t make_evict_last_policy() {
    uint64_t pol;
    asm("createpolicy.fractional.L2::evict_last.b64 %0, 1.0;" : "=l"(pol));
    return pol;
}

static __device__ __forceinline__ float ldg_pin_l2(const float* p, uint64_t pol) {
    float v;
    asm("ld.global.nc.L2::cache_hint.f32 %0, [%1], %2;"
        : "=f"(v) : "l"(p), "l"(pol));
    return v;
}

__global__ void __launch_bounds__(256) voxel_gather_kernel(
    const float4* __restrict__ x4,   // 3 float4s per 4 points
    const float*  __restrict__ f,    // 256^3 grid
    float4*       __restrict__ out4, // 1 float4 per 4 points
    int n4)                          // number of 4-point groups
{
    int t = blockIdx.x * blockDim.x + threadIdx.x;
    if (t >= n4) return;

    const uint64_t pol = make_evict_last_policy();

    const float4* p = x4 + 3 * (size_t)t;
    float4 a = __ldcs(p + 0);   // streaming: evict-first, keep L2 for f
    float4 b = __ldcs(p + 1);
    float4 c = __ldcs(p + 2);

    // point 0: (a.x, a.y, a.z)  point 1: (a.w, b.x, b.y)
    // point 2: (b.z, b.w, c.x)  point 3: (c.y, c.z, c.w)
    int i0 = (vox1(a.x) << 16) | (vox1(a.y) << 8) | vox1(a.z);
    int i1 = (vox1(a.w) << 16) | (vox1(b.x) << 8) | vox1(b.y);
    int i2 = (vox1(b.z) << 16) | (vox1(b.w) << 8) | vox1(c.x);
    int i3 = (vox1(c.y) << 16) | (vox1(c.z) << 8) | vox1(c.w);

    float4 o;
    o.x = ldg_pin_l2(f + i0, pol);   // evict_last: pin gather table in L2
    o.y = ldg_pin_l2(f + i1, pol);
    o.z = ldg_pin_l2(f + i2, pol);
    o.w = ldg_pin_l2(f + i3, pol);
    __stcs(out4 + t, o);             // streaming store
}

// Tail handler for n not divisible by 4 (not needed for 16777216, but cheap).
__global__ void voxel_gather_tail_kernel(
    const float* __restrict__ x,
    const float* __restrict__ f,
    float*       __restrict__ out,
    int start, int n)
{
    int i = start + blockIdx.x * blockDim.x + threadIdx.x;
    if (i >= n) return;
    const uint64_t pol = make_evict_last_policy();
    int ix = vox1(x[3 * (size_t)i + 0]);
    int iy = vox1(x[3 * (size_t)i + 1]);
    int iz = vox1(x[3 * (size_t)i + 2]);
    out[i] = ldg_pin_l2(f + ((ix << 16) | (iy << 8) | iz), pol);
}

extern "C" void kernel_launch(void* const* d_in, const int* in_sizes, int n_in,
                              void* d_out, int out_size) {
    const float* x = (const float*)d_in[0];   // (N, 3) fp32
    const float* f = (const float*)d_in[1];   // (256,256,256) fp32
    float* out = (float*)d_out;               // (N,) fp32

    int n  = in_sizes[0] / 3;                 // number of points
    int n4 = n / 4;

    if (n4 > 0) {
        int threads = 256;
        int blocks = (n4 + threads - 1) / threads;
        voxel_gather_kernel<<<blocks, threads>>>(
            (const float4*)x, f, (float4*)out, n4);
    }
    int rem_start = n4 * 4;
    if (rem_start < n) {
        int rem = n - rem_start;
        voxel_gather_tail_kernel<<<(rem + 255) / 256, 256>>>(
            x, f, out, rem_start, n);
    }
}

// round 9
// speedup vs baseline: 1.0748x; 1.0241x over previous
#include <cuda_runtime.h>
#include <cstdint>

// ModelVoxel: out[p] = f[i,j,k] with i,j,k = (int)clip((x[p]+1)/h, 0, 255),
// h = 2/255, f is 256^3 fp32 (64 MB, fits in GB300's ~126 MB L2).
//
// R7: cache-priority separation, fixed encoding.
//  - x (192 MB, read-once)  -> __ldcs (L2 evict-first, don't pollute)
//  - out (64 MB, write-once)-> __stcs (streaming store)
//  - f  (64 MB gather table)-> ld.global.nc.L2::cache_hint with a
//    createpolicy.fractional.L2::evict_last policy register (ptxas rejects
//    the immediate .L2::evict_last form on scalar loads on sm_103).
// Goal: keep f fully L2-resident so the 16.7M random gathers never hit DRAM.

static __device__ __forceinline__ int vox1(float v) {
    const float h = 2.0f / 255.0f;           // replicate reference's fp32 h
    float p = (v + 1.0f) / h;                // same op order as reference
    p = fminf(fmaxf(p, 0.0f), 255.0f);       // clip
    return (int)p;                           // truncation == astype(int32) (p >= 0)
}

static __device__ __forceinline__ uint64_t make_evict_last_policy() {
    uint64_t pol;
    asm("createpolicy.fractional.L2::evict_last.b64 %0, 1.0;" : "=l"(pol));
    return pol;
}

static __device__ __forceinline__ float ldg_pin_l2(const float* p, uint64_t pol) {
    float v;
    asm("ld.global.nc.L2::cache_hint.f32 %0, [%1], %2;"
        : "=f"(v) : "l"(p), "l"(pol));
    return v;
}

__global__ void __launch_bounds__(256) voxel_gather_kernel(
    const float4* __restrict__ x4,   // 3 float4s per 4 points
    const float*  __restrict__ f,    // 256^3 grid
    float4*       __restrict__ out4, // 1 float4 per 4 points
    int n4)                          // number of 4-point groups
{
    int t = blockIdx.x * blockDim.x + threadIdx.x;
    if (t >= n4) return;

    const uint64_t pol = make_evict_last_policy();

    const float4* p = x4 + 3 * (size_t)t;
    float4 a = __ldcs(p + 0);   // streaming: evict-first, keep L2 for f
    float4 b = __ldcs(p + 1);
    float4 c = __ldcs(p + 2);

    // point 0: (a.x, a.y, a.z)  point 1: (a.w, b.x, b.y)
    // point 2: (b.z, b.w, c.x)  point 3: (c.y, c.z, c.w)
    int i0 = (vox1(a.x) << 16) | (vox1(a.y) << 8) | vox1(a.z);
    int i1 = (vox1(a.w) << 16) | (vox1(b.x) << 8) | vox1(b.y);
    int i2 = (vox1(b.z) << 16) | (vox1(b.w) << 8) | vox1(c.x);
    int i3 = (vox1(c.y) << 16) | (vox1(c.z) << 8) | vox1(c.w);

    float4 o;
    o.x = ldg_pin_l2(f + i0, pol);   // evict_last: pin gather table in L2
    o.y = ldg_pin_l2(f + i1, pol);
    o.z = ldg_pin_l2(f + i2, pol);
    o.w = ldg_pin_l2(f + i3, pol);
    __stcs(out4 + t, o);             // streaming store
}

// Tail handler for n not divisible by 4 (not needed for 16777216, but cheap).
__global__ void voxel_gather_tail_kernel(
    const float* __restrict__ x,
    const float* __restrict__ f,
    float*       __restrict__ out,
    int start, int n)
{
    int i = start + blockIdx.x * blockDim.x + threadIdx.x;
    if (i >= n) return;
    const uint64_t pol = make_evict_last_policy();
    int ix = vox1(x[3 * (size_t)i + 0]);
    int iy = vox1(x[3 * (size_t)i + 1]);
    int iz = vox1(x[3 * (size_t)i + 2]);
    out[i] = ldg_pin_l2(f + ((ix << 16) | (iy << 8) | iz), pol);
}

extern "C" void kernel_launch(void* const* d_in, const int* in_sizes, int n_in,
                              void* d_out, int out_size) {
    const float* x = (const float*)d_in[0];   // (N, 3) fp32
    const float* f = (const float*)d_in[1];   // (256,256,256) fp32
    float* out = (float*)d_out;               // (N,) fp32

    int n  = in_sizes[0] / 3;                 // number of points
    int n4 = n / 4;

    if (n4 > 0) {
        int threads = 256;
        int blocks = (n4 + threads - 1) / threads;
        voxel_gather_kernel<<<blocks, threads>>>(
            (const float4*)x, f, (float4*)out, n4);
    }
    int rem_start = n4 * 4;
    if (rem_start < n) {
        int rem = n - rem_start;
        voxel_gather_tail_kernel<<<(rem + 255) / 256, 256>>>(
            x, f, out, rem_start, n);
    }
}